// round 2
// baseline (speedup 1.0000x reference)
#include <cuda_runtime.h>

// Covariance over time axis: x [64, 4, 8192, 16] fp32 -> cov [64, 4, 16, 16]
// cov = (Sum_t x_m x_n - s_m s_n / T) / (T-1)
//
// Symmetry-exploiting version: only the 10 upper-triangle 4x4 blocks of the
// 16x16 output are accumulated. One warp per block, one lane per time-row.
//
// Kernel 1: 256 slices x 4 T-chunks; each CTA (320 thr = 10 warps) computes
//           partial S over its 2048-row chunk + colsums, warp-shfl reduction,
//           writes to __device__ scratch (deterministic, no atomics).
// Kernel 2: folds the 4 chunk partials, applies mean correction, mirrors
//           the lower triangle.

#define T_TOTAL   8192
#define M_DIM     16
#define NCHUNK    4
#define CHUNK     (T_TOTAL / NCHUNK)     // 2048 rows
#define TILE_ROWS 128
#define NTILES    (CHUNK / TILE_ROWS)    // 16
#define NSLICE    256
#define NBLK      10                     // upper-triangle 4x4 blocks
#define ROW_S     20                     // padded smem row stride (floats)
#define PART_STRIDE 176                  // 160 (tri blocks) + 16 (colsum)

__device__ float g_partial[NSLICE * NCHUNK * PART_STRIDE];

__global__ __launch_bounds__(320, 4)
void cov_partial_kernel(const float* __restrict__ x) {
    // tile: 128 rows x ROW_S floats = 2560 floats (10 KB)
    __shared__ float sm[TILE_ROWS * ROW_S];

    const int bx    = blockIdx.x;
    const int slice = bx & (NSLICE - 1);
    const int chunk = bx >> 8;                 // 0..3
    const int tid   = threadIdx.x;
    const int warp  = tid >> 5;                // block id 0..9
    const int lane  = tid & 31;

    // block (bi, bj), bi <= bj, enumeration:
    // (0,0)=0 (0,1)=1 (0,2)=2 (0,3)=3 (1,1)=4 (1,2)=5 (1,3)=6 (2,2)=7 (2,3)=8 (3,3)=9
    const int bi = (warp < 4) ? 0 : (warp < 7) ? 1 : (warp < 9) ? 2 : 3;
    const int off = (bi == 0) ? 0 : (bi == 1) ? 4 : (bi == 2) ? 7 : 9;
    const int bj = bi + (warp - off);
    const bool diag = (bi == bj);

    const float4* gx = (const float4*)x;
    // float4 units: slice stride = 8192*16/4 = 32768; chunk stride = 2048*16/4 = 8192
    long base = (long)slice * (T_TOTAL * M_DIM / 4) + (long)chunk * (CHUNK * M_DIM / 4);

    float acc[16];
#pragma unroll
    for (int i = 0; i < 16; i++) acc[i] = 0.f;
    float cs[4] = {0.f, 0.f, 0.f, 0.f};

    // tile = 512 float4; threads 0..255 load 2 each
    float4 r0, r1;
    if (tid < 256) {
        r0 = gx[base + tid];
        r1 = gx[base + 256 + tid];
    }

    for (int tile = 0; tile < NTILES; ++tile) {
        if (tid < 256) {
            // idx = tid -> row = tid/4, quad = tid%4 ; padded-row store
            int row0 = tid >> 2, q0 = tid & 3;
            *(float4*)(sm + row0 * ROW_S + q0 * 4) = r0;
            *(float4*)(sm + (row0 + 64) * ROW_S + q0 * 4) = r1;
        }
        __syncthreads();

        if (tile + 1 < NTILES && tid < 256) {
            long nb = base + (long)(tile + 1) * 512;
            r0 = gx[nb + tid];
            r1 = gx[nb + 256 + tid];
        }

#pragma unroll
        for (int r = 0; r < TILE_ROWS / 32; ++r) {
            const int row = r * 32 + lane;
            const float* rp = sm + row * ROW_S;
            float4 a = *(const float4*)(rp + 4 * bi);
            float4 c = *(const float4*)(rp + 4 * bj);

            acc[ 0] = fmaf(a.x, c.x, acc[ 0]);
            acc[ 1] = fmaf(a.x, c.y, acc[ 1]);
            acc[ 2] = fmaf(a.x, c.z, acc[ 2]);
            acc[ 3] = fmaf(a.x, c.w, acc[ 3]);
            acc[ 4] = fmaf(a.y, c.x, acc[ 4]);
            acc[ 5] = fmaf(a.y, c.y, acc[ 5]);
            acc[ 6] = fmaf(a.y, c.z, acc[ 6]);
            acc[ 7] = fmaf(a.y, c.w, acc[ 7]);
            acc[ 8] = fmaf(a.z, c.x, acc[ 8]);
            acc[ 9] = fmaf(a.z, c.y, acc[ 9]);
            acc[10] = fmaf(a.z, c.z, acc[10]);
            acc[11] = fmaf(a.z, c.w, acc[11]);
            acc[12] = fmaf(a.w, c.x, acc[12]);
            acc[13] = fmaf(a.w, c.y, acc[13]);
            acc[14] = fmaf(a.w, c.z, acc[14]);
            acc[15] = fmaf(a.w, c.w, acc[15]);

            if (diag) {   // diagonal-block warps also accumulate column sums
                cs[0] += a.x; cs[1] += a.y; cs[2] += a.z; cs[3] += a.w;
            }
        }
        __syncthreads();
    }

    // ---- warp-level butterfly reduction (block is warp-uniform) ----
#pragma unroll
    for (int o = 16; o >= 1; o >>= 1) {
#pragma unroll
        for (int i = 0; i < 16; i++) acc[i] += __shfl_xor_sync(0xffffffffu, acc[i], o);
        if (diag) {
#pragma unroll
            for (int i = 0; i < 4; i++) cs[i] += __shfl_xor_sync(0xffffffffu, cs[i], o);
        }
    }

    float* part = &g_partial[(slice * NCHUNK + chunk) * PART_STRIDE];
    if (lane < 16) {
        // entry i = p*4+q : S[4*bi+p][4*bj+q]
        float v = (lane == 0)  ? acc[0]  : (lane == 1)  ? acc[1]  :
                  (lane == 2)  ? acc[2]  : (lane == 3)  ? acc[3]  :
                  (lane == 4)  ? acc[4]  : (lane == 5)  ? acc[5]  :
                  (lane == 6)  ? acc[6]  : (lane == 7)  ? acc[7]  :
                  (lane == 8)  ? acc[8]  : (lane == 9)  ? acc[9]  :
                  (lane == 10) ? acc[10] : (lane == 11) ? acc[11] :
                  (lane == 12) ? acc[12] : (lane == 13) ? acc[13] :
                  (lane == 14) ? acc[14] : acc[15];
        part[warp * 16 + lane] = v;
    }
    if (diag && lane < 4) {
        float v = (lane == 0) ? cs[0] : (lane == 1) ? cs[1] : (lane == 2) ? cs[2] : cs[3];
        part[160 + bi * 4 + lane] = v;       // colsum for m = 4*bi + lane
    }
}

__global__ __launch_bounds__(256)
void cov_final_kernel(float* __restrict__ out) {
    const int s   = blockIdx.x;
    const int tid = threadIdx.x;        // tid = m*16 + n
    int m = tid >> 4;
    int n = tid & 15;

    int bi = m >> 2, bj = n >> 2;
    int mm = m, nn = n;
    if (bi > bj) { mm = n; nn = m; int t = bi; bi = bj; bj = t; }
    const int off = (bi == 0) ? 0 : (bi == 1) ? 4 : (bi == 2) ? 7 : 9;
    const int blk = off + (bj - bi);
    const int entry = (mm & 3) * 4 + (nn & 3);

    const float* p = &g_partial[s * NCHUNK * PART_STRIDE];
    float S = 0.f, sm_ = 0.f, sn_ = 0.f;
#pragma unroll
    for (int c = 0; c < NCHUNK; ++c) {
        S   += p[c * PART_STRIDE + blk * 16 + entry];
        sm_ += p[c * PART_STRIDE + 160 + m];
        sn_ += p[c * PART_STRIDE + 160 + n];
    }
    const float inv_T  = 1.0f / (float)T_TOTAL;
    const float inv_T1 = 1.0f / (float)(T_TOTAL - 1);
    out[s * 256 + tid] = (S - sm_ * sn_ * inv_T) * inv_T1;
}

extern "C" void kernel_launch(void* const* d_in, const int* in_sizes, int n_in,
                              void* d_out, int out_size) {
    const float* x = (const float*)d_in[0];
    float* out = (float*)d_out;
    cov_partial_kernel<<<NSLICE * NCHUNK, 320>>>(x);
    cov_final_kernel<<<NSLICE, 256>>>(out);
}